// round 17
// baseline (speedup 1.0000x reference)
#include <cuda_runtime.h>
#include <cstdint>

// Problem constants
#define BB    128
#define LL    9
#define KK    3
#define PP    1680
#define CIN   256
#define COUT  256
#define ZR    1152
#define ZC    768
#define KSPLIT 2

typedef unsigned long long u64;

// Scratch (device globals: allocation-free)
__device__ float  g_Z[KSPLIT * ZR * ZC];   // 6.8 MB, 2 K-partials
__device__ int    g_codes[PP];             // c0 (base-3 of l=0..3) | c1<<8 (l=4..8)

__device__ __forceinline__ u64 pack2(float lo, float hi) {
    u64 r;
    asm("mov.b64 %0, {%1, %2};" : "=l"(r) : "f"(lo), "f"(hi));
    return r;
}
__device__ __forceinline__ void unpack2(float& lo, float& hi, u64 v) {
    asm("mov.b64 {%0, %1}, %2;" : "=f"(lo), "=f"(hi) : "l"(v));
}
__device__ __forceinline__ void ffma2(u64& d, u64 a, u64 b) {
    asm("fma.rn.f32x2 %0, %1, %2, %3;" : "=l"(d) : "l"(a), "l"(b), "l"(d));
}

// Swizzled transposed tile: logical [c][r]
// physical float offset = c*64 + 4*((r>>2) ^ ((c>>2)&15)) + (r&3)

// ---------------------------------------------------------------------------
// Kernel 1: GEMM partial. Z[ks][r,j] = sum_{c in ks*128..+128} X[r,c]*Wm[j,c]
// 64x64 tile, two 64-wide K chunks, XOR-swizzled transposed smem tiles,
// 4x4 reg tile via packed f32x2 FMAs, register prefetch. grid=(18,12,2).
// Blocks (bx<7, by==0, bz==0) also decode permutation codes from M (4+5 split).
// ---------------------------------------------------------------------------
__global__ void __launch_bounds__(256) gemm_z(const float* __restrict__ X,
                                              const float* __restrict__ Wm,
                                              const float* __restrict__ M) {
    __shared__ float sX[64 * 64];
    __shared__ float sW[64 * 64];

    const int t  = threadIdx.x;
    const int rb = blockIdx.x * 64;
    const int jb = blockIdx.y * 64;
    const int kb = blockIdx.z * 128;

    // fused code decode (7 blocks x 256 threads >= 1680), 4+5 split
    if (blockIdx.y == 0 && blockIdx.z == 0 && blockIdx.x < 7) {
        int p = blockIdx.x * 256 + t;
        if (p < PP) {
            const int PL = PP * LL;
            int c0 = 0, c1 = 0;
            const int w9[9] = {1, 3, 9, 27, 1, 3, 9, 27, 81};
#pragma unroll
            for (int l = 0; l < LL; l++) {
                float m1 = M[PL + p * LL + l];
                float m2 = M[2 * PL + p * LL + l];
                int a = (m1 > 0.5f) ? 1 : ((m2 > 0.5f) ? 2 : 0);
                if (l < 4) c0 += a * w9[l];
                else       c1 += a * w9[l];
            }
            g_codes[p] = c0 | (c1 << 8);
        }
    }

    const int c4 = t & 15;
    const int rr = t >> 4;

    const int gx = t >> 4;
    const int gw = t & 15;
    const int row0 = gx * 4;
    const int col0 = gw * 4;

    u64 ap0[4] = {0, 0, 0, 0};
    u64 ap1[4] = {0, 0, 0, 0};

#pragma unroll
    for (int kk = 0; kk < 2; kk++) {
        const int kc = kb + kk * 64;
#pragma unroll
        for (int i = 0; i < 4; i++) {
            int r = rr + i * 16;
            int gs = (((r >> 2) ^ c4) << 2) + (r & 3);
            float4 v = *(const float4*)&X[(rb + r) * CIN + kc + c4 * 4];
            float* px = &sX[c4 * 256 + gs];
            px[0]   = v.x;
            px[64]  = v.y;
            px[128] = v.z;
            px[192] = v.w;
            float4 w = *(const float4*)&Wm[(jb + r) * CIN + kc + c4 * 4];
            float* pw = &sW[c4 * 256 + gs];
            pw[0]   = w.x;
            pw[64]  = w.y;
            pw[128] = w.z;
            pw[192] = w.w;
        }
        __syncthreads();

        ulonglong2 xp = *(const ulonglong2*)&sX[(gx ^ 0) << 2];
        float4     wv = *(const float4*)&sW[(gw ^ 0) << 2];
#pragma unroll
        for (int c = 0; c < 64; c++) {
            ulonglong2 xc = xp;
            float4 wc = wv;
            if (c < 63) {
                int key = ((c + 1) >> 2) & 15;
                xp = *(const ulonglong2*)&sX[(c + 1) * 64 + ((gx ^ key) << 2)];
                wv = *(const float4*)&sW[(c + 1) * 64 + ((gw ^ key) << 2)];
            }
            u64 w0 = pack2(wc.x, wc.x);
            u64 w1 = pack2(wc.y, wc.y);
            u64 w2 = pack2(wc.z, wc.z);
            u64 w3 = pack2(wc.w, wc.w);
            ffma2(ap0[0], xc.x, w0);
            ffma2(ap0[1], xc.x, w1);
            ffma2(ap0[2], xc.x, w2);
            ffma2(ap0[3], xc.x, w3);
            ffma2(ap1[0], xc.y, w0);
            ffma2(ap1[1], xc.y, w1);
            ffma2(ap1[2], xc.y, w2);
            ffma2(ap1[3], xc.y, w3);
        }
        __syncthreads();
    }

    float acc[4][4];
#pragma unroll
    for (int j = 0; j < 4; j++) {
        unpack2(acc[0][j], acc[1][j], ap0[j]);
        unpack2(acc[2][j], acc[3][j], ap1[j]);
    }
    float4* Z4 = (float4*)(g_Z + blockIdx.z * (ZR * ZC));
#pragma unroll
    for (int i = 0; i < 4; i++) {
        float4 v = make_float4(acc[i][0], acc[i][1], acc[i][2], acc[i][3]);
        Z4[(rb + row0 + i) * (ZC / 4) + (jb + col0) / 4] = v;
    }
}

// ---------------------------------------------------------------------------
// Kernel 2 (fused): combine with 4+5 position split -> 2 LDS per output.
// T0[81] over l=0..3, T1[243] over l=4..8, channel-eighth blocks (Q4=8 f4).
// grid = (3 p-chunks of 560, 8 channel eighths, 128 b), 512 threads.
// smem = 10.1 + 30.4 + 3.4 + 2.2 KB = 46.1 KB -> 4 CTAs/SM, 2048 thr = full.
// ---------------------------------------------------------------------------
#define PCHUNK 560
#define NCHUNK 3
#define Q4     8           // float4 per channel eighth

__global__ void __launch_bounds__(512) perm_combine(float* __restrict__ out) {
    __shared__ float4 sT0[81 * Q4];
    __shared__ float4 sT1[243 * Q4];
    __shared__ float4 sZ[27 * Q4];
    __shared__ int sCodes[PCHUNK];

    const int t     = threadIdx.x;
    const int chunk = blockIdx.x;
    const int h     = blockIdx.y;   // channel eighth 0..7
    const int b     = blockIdx.z;
    const int pbase = chunk * PCHUNK;

    // ---- stage summed Z slice (both K-partials): vr = l*3 + k ----
    const float4* Z0 = (const float4*)g_Z;
    const int pstride = (ZR * ZC) / 4;
    const int zb = b * LL * (ZC / 4) + h * Q4;
    for (int i = t; i < 27 * Q4; i += 512) {
        int vr = i >> 3;
        int o4 = i & (Q4 - 1);
        int l = vr / 3, k = vr - 3 * l;
        int idx = zb + l * (ZC / 4) + k * (COUT / 4) + o4;
        float4 a = Z0[idx];
        float4 bb = Z0[idx + pstride];
        float4 s;
        s.x = a.x + bb.x;
        s.y = a.y + bb.y;
        s.z = a.z + bb.z;
        s.w = a.w + bb.w;
        sZ[i] = s;
    }
    for (int i = t; i < PCHUNK; i += 512) sCodes[i] = g_codes[pbase + i];
    __syncthreads();

    // ---- build T0 (81 entries over positions l=0..3) ----
#pragma unroll 2
    for (int i = t; i < 81 * Q4; i += 512) {
        int c  = i >> 3;
        int o4 = i & (Q4 - 1);
        int d0 = c % 3, d1 = (c / 3) % 3, d2 = (c / 9) % 3, d3 = c / 27;
        float4 v0 = sZ[(0 + d0) * Q4 + o4];
        float4 v1 = sZ[(3 + d1) * Q4 + o4];
        float4 v2 = sZ[(6 + d2) * Q4 + o4];
        float4 v3 = sZ[(9 + d3) * Q4 + o4];
        float4 s;
        s.x = (v0.x + v1.x) + (v2.x + v3.x);
        s.y = (v0.y + v1.y) + (v2.y + v3.y);
        s.z = (v0.z + v1.z) + (v2.z + v3.z);
        s.w = (v0.w + v1.w) + (v2.w + v3.w);
        sT0[i] = s;
    }
    // ---- build T1 (243 entries over positions l=4..8) ----
#pragma unroll 2
    for (int i = t; i < 243 * Q4; i += 512) {
        int c  = i >> 3;
        int o4 = i & (Q4 - 1);
        int d0 = c % 3, d1 = (c / 3) % 3, d2 = (c / 9) % 3;
        int d3 = (c / 27) % 3, d4 = c / 81;
        float4 v0 = sZ[(12 + d0) * Q4 + o4];
        float4 v1 = sZ[(15 + d1) * Q4 + o4];
        float4 v2 = sZ[(18 + d2) * Q4 + o4];
        float4 v3 = sZ[(21 + d3) * Q4 + o4];
        float4 v4 = sZ[(24 + d4) * Q4 + o4];
        float4 s;
        s.x = ((v0.x + v1.x) + (v2.x + v3.x)) + v4.x;
        s.y = ((v0.y + v1.y) + (v2.y + v3.y)) + v4.y;
        s.z = ((v0.z + v1.z) + (v2.z + v3.z)) + v4.z;
        s.w = ((v0.w + v1.w) + (v2.w + v3.w)) + v4.w;
        sT1[i] = s;
    }
    __syncthreads();

    // ---- combine + stream out: 8 threads per p-row, 64 p per iter ----
    const int o4 = t & (Q4 - 1);
    const int pw = t >> 3;           // 0..63
    float4* out4 = (float4*)out;
    const int obase = (b * PP + pbase) * (COUT / 4) + h * Q4 + o4;

#pragma unroll 3
    for (int it = 0; it < (PCHUNK + 63) / 64; it++) {
        int po = it * 64 + pw;
        if (po < PCHUNK) {
            int code = sCodes[po];
            int c0 = code & 0xFF;
            int c1 = (code >> 8) & 0xFF;
            float4 a  = sT0[c0 * Q4 + o4];
            float4 bb = sT1[c1 * Q4 + o4];
            float4 r;
            r.x = a.x + bb.x;
            r.y = a.y + bb.y;
            r.z = a.z + bb.z;
            r.w = a.w + bb.w;
            __stcs(&out4[obase + po * (COUT / 4)], r);
        }
    }
}

// ---------------------------------------------------------------------------
extern "C" void kernel_launch(void* const* d_in, const int* in_sizes, int n_in,
                              void* d_out, int out_size) {
    (void)in_sizes; (void)n_in; (void)out_size;
    const float* x = (const float*)d_in[0];  // (128, 9, 256)
    const float* W = (const float*)d_in[1];  // (3, 256, 256)
    const float* M = (const float*)d_in[2];  // (3, 1680, 9)
    float* out = (float*)d_out;              // (128, 1680, 256)

    gemm_z<<<dim3(18, 12, KSPLIT), 256>>>(x, W, M);
    perm_combine<<<dim3(NCHUNK, 8, BB), 512>>>(out);
}